// round 7
// baseline (speedup 1.0000x reference)
#include <cuda_runtime.h>

// ---------------------------------------------------------------------------
// ChebConv x4 GNN on GB300.  N=100000 nodes, E=1600000 directed edges
// (symmetrized), HID=128, K=4 Chebyshev order.
//
// Pipeline per launch (all graph-capturable, allocation-free):
//   1. build CSR by dst (counting sort: atomic count -> 1-block scan+dinv ->
//      fill)
//   2. layer1 (3-wide): cheb on x, small GEMM K=12 (+fused BN stats), leaky
//   3. layers 2-4 (128-wide): 3 SpMMs each (warp-per-row, float4 lanes,
//      all-lane broadcast edge headers, Chebyshev recurrence fused), one
//      K=512 fp32 GEMM (f32x2 packed FFMA) with activation + fused BN stats
//      into a PER-LAYER stat buffer; BN applied inside k_apply (no separate
//      bnparam launch)
//   4. row L2-normalize + [128x3] head -> d_out
// ---------------------------------------------------------------------------

#define NNODES 100000
#define NEDGES 1600000
#define HIDDEN 128
#define NEG_SLOPE 0.01f

// ------------------------------- scratch -----------------------------------
__device__ float g_A[(size_t)NNODES * 512];   // [T0|T1|T2|T3] per row, 512 f32
__device__ float g_Y[(size_t)NNODES * HIDDEN];
__device__ float g_A1[(size_t)NNODES * 12];   // layer-1 [T0|T1|T2|T3] x 3
__device__ int   g_deg[NNODES];
__device__ int   g_cur[NNODES];
__device__ int   g_rowptr[NNODES + 1];
__device__ int2  g_edge[NEDGES];              // (col, enorm-bits) interleaved
__device__ float g_dinv[NNODES];
__device__ float g_colsum[3][HIDDEN];         // per-BN-layer stats
__device__ float g_colsumsq[3][HIDDEN];
__device__ int   g_estride;                   // 1 = int32 edges, 2 = int64

// ------------------------------ helpers ------------------------------------
__device__ __forceinline__ void ffma2(float2& d, const float2 a, const float2 b) {
    asm volatile("fma.rn.f32x2 %0, %1, %2, %0;"
                 : "+l"(reinterpret_cast<unsigned long long&>(d))
                 : "l"(reinterpret_cast<const unsigned long long&>(a)),
                   "l"(reinterpret_cast<const unsigned long long&>(b)));
}

// ------------------------------ CSR build ----------------------------------
// init counters + stage x into the layer-1 feature block (fused elementwise).
__global__ void k_init(const float* __restrict__ x) {
    int i = blockIdx.x * blockDim.x + threadIdx.x;
    int gs = gridDim.x * blockDim.x;
    for (int j = i; j < NNODES; j += gs) {
        g_deg[j] = 0;
        g_cur[j] = 0;
        g_A1[j * 12 + 0] = x[j * 3 + 0];
        g_A1[j * 12 + 1] = x[j * 3 + 1];
        g_A1[j * 12 + 2] = x[j * 3 + 2];
    }
    if (blockIdx.x == 0 && threadIdx.x < HIDDEN) {
        for (int l = 0; l < 3; l++) {
            g_colsum[l][threadIdx.x] = 0.f;
            g_colsumsq[l][threadIdx.x] = 0.f;
        }
    }
}

// Detect whether the edge buffer is int32 (stride 1) or int64 (stride 2).
// int64 little-endian: every odd 32-bit word is a zero high-word (indices
// < 100000 so high words are 0; random int32 sources make this test robust).
__global__ void k_detect(const int* __restrict__ ed, int nelem) {
    int lane = threadIdx.x;
    bool any = false;
    for (int i = 1 + 2 * lane; i < 4096; i += 64) any |= (ed[i] != 0);
    any = __any_sync(0xffffffffu, any);
    if (lane == 0) g_estride = any ? 1 : 2;
}

// dst = second row of edge_index; coalesced 64-bit reads in the int64 case.
__global__ void k_count(const int* __restrict__ ed) {
    int st = g_estride;
    int i = blockIdx.x * blockDim.x + threadIdx.x;
    int gs = gridDim.x * blockDim.x;
    if (st == 1) {
        const int* dstp = ed + NEDGES;
        for (int e = i; e < NEDGES; e += gs)
            atomicAdd(&g_deg[dstp[e]], 1);
    } else {
        const long long* dstp = (const long long*)ed + NEDGES;
        for (int e = i; e < NEDGES; e += gs)
            atomicAdd(&g_deg[(int)dstp[e]], 1);
    }
}

// exclusive scan of g_deg -> g_rowptr, plus dinv = rsqrt(deg) on the fly.
__global__ void k_scan() {   // single block, 1024 threads
    __shared__ int sh[1024];
    int t = threadIdx.x;
    const int IT = (NNODES + 1023) / 1024;   // 98
    int base = t * IT;
    int s = 0;
    for (int j = 0; j < IT; j++) { int idx = base + j; if (idx < NNODES) s += g_deg[idx]; }
    sh[t] = s;
    __syncthreads();
    for (int off = 1; off < 1024; off <<= 1) {
        int v = (t >= off) ? sh[t - off] : 0;
        __syncthreads();
        sh[t] += v;
        __syncthreads();
    }
    int run = (t > 0) ? sh[t - 1] : 0;
    for (int j = 0; j < IT; j++) {
        int idx = base + j;
        if (idx < NNODES) {
            int d = g_deg[idx];
            g_rowptr[idx] = run;
            run += d;
            g_dinv[idx] = (d > 0) ? rsqrtf((float)d) : 0.f;
        }
    }
    if (t == 1023) g_rowptr[NNODES] = sh[1023];
}

__global__ void k_fill(const int* __restrict__ ed) {
    int st = g_estride;
    int i = blockIdx.x * blockDim.x + threadIdx.x;
    int gs = gridDim.x * blockDim.x;
    if (st == 1) {
        const int* srcp = ed;
        const int* dstp = ed + NEDGES;
        for (int e = i; e < NEDGES; e += gs) {
            int s = srcp[e], d = dstp[e];
            int pos = g_rowptr[d] + atomicAdd(&g_cur[d], 1);
            float w = -g_dinv[s] * g_dinv[d];
            g_edge[pos] = make_int2(s, __float_as_int(w));
        }
    } else {
        const long long* srcp = (const long long*)ed;
        const long long* dstp = (const long long*)ed + NEDGES;
        for (int e = i; e < NEDGES; e += gs) {
            int s = (int)srcp[e], d = (int)dstp[e];
            int pos = g_rowptr[d] + atomicAdd(&g_cur[d], 1);
            float w = -g_dinv[s] * g_dinv[d];
            g_edge[pos] = make_int2(s, __float_as_int(w));
        }
    }
}

// --------------------------- layer 1 (3-wide) ------------------------------
__global__ void k_spmm3(int in_off, int out_off, int prev_off, int mode) {
    int i = blockIdx.x * blockDim.x + threadIdx.x;
    int gs = gridDim.x * blockDim.x;
    for (int r = i; r < NNODES; r += gs) {
        int b = g_rowptr[r], e2 = g_rowptr[r + 1];
        float a0 = 0.f, a1 = 0.f, a2 = 0.f;
        for (int e = b; e < e2; e++) {
            int2 ew = g_edge[e];
            float w = __int_as_float(ew.y);
            const float* p = &g_A1[(size_t)ew.x * 12 + in_off];
            a0 += w * p[0]; a1 += w * p[1]; a2 += w * p[2];
        }
        if (mode) {
            const float* pr = &g_A1[(size_t)r * 12 + prev_off];
            a0 = 2.f * a0 - pr[0]; a1 = 2.f * a1 - pr[1]; a2 = 2.f * a2 - pr[2];
        }
        float* q = &g_A1[(size_t)r * 12 + out_off];
        q[0] = a0; q[1] = a1; q[2] = a2;
    }
}

// K=12 GEMM + leaky + fused BN-stats accumulation (layer-0 stats).
__global__ void k_gemm12(const float* __restrict__ W, const float* __restrict__ bias) {
    __shared__ float Ws[12 * 128];
    int c = threadIdx.x;
    for (int j = 0; j < 12; j++) Ws[j * 128 + c] = W[j * 128 + c];
    __syncthreads();
    float b = bias[c];
    float s = 0.f, s2 = 0.f;
    for (int i = blockIdx.x; i < NNODES; i += gridDim.x) {
        const float* ar = &g_A1[(size_t)i * 12];
        float acc = b;
#pragma unroll
        for (int j = 0; j < 12; j++) acc += ar[j] * Ws[j * 128 + c];
        acc = (acc >= 0.f) ? acc : NEG_SLOPE * acc;   // leaky
        g_Y[(size_t)i * 128 + c] = acc;
        s += acc; s2 += acc * acc;
    }
    atomicAdd(&g_colsum[0][c], s);
    atomicAdd(&g_colsumsq[0][c], s2);
}

// ------------------------------ BN apply ------------------------------------
// Each block derives scale/shift from the layer's stat buffers (128 rsqrtf,
// once per block), then streams h = Y*scale + shift into A block 0.
__global__ void __launch_bounds__(256) k_apply(const float* __restrict__ gamma,
                                               const float* __restrict__ beta,
                                               int layer) {
    __shared__ float s_scale[HIDDEN];
    __shared__ float s_shift[HIDDEN];
    int t = threadIdx.x;
    if (t < HIDDEN) {
        const float inv_n = 1.0f / (float)NNODES;
        float mu = g_colsum[layer][t] * inv_n;
        float var = fmaxf(g_colsumsq[layer][t] * inv_n - mu * mu, 0.f);
        float sc = gamma[t] * rsqrtf(var + 1e-5f);
        s_scale[t] = sc;
        s_shift[t] = beta[t] - mu * sc;
    }
    __syncthreads();

    int i = blockIdx.x * blockDim.x + t;
    int gs = gridDim.x * blockDim.x;
    const int tot = NNODES * 32;   // float4 groups
    for (int idx = i; idx < tot; idx += gs) {
        int row = idx >> 5;
        int c4 = idx & 31;
        float4 y = *(const float4*)&g_Y[(size_t)row * 128 + c4 * 4];
        float4 sc = *(const float4*)&s_scale[c4 * 4];
        float4 sh = *(const float4*)&s_shift[c4 * 4];
        float4 r;
        r.x = y.x * sc.x + sh.x;
        r.y = y.y * sc.y + sh.y;
        r.z = y.z * sc.z + sh.z;
        r.w = y.w * sc.w + sh.w;
        *(float4*)&g_A[(size_t)row * 512 + c4 * 4] = r;
    }
}

// --------------------------- 128-wide SpMM ---------------------------------
// Warp per row; each lane owns 4 consecutive columns (float4).  Edge headers
// loaded by ALL lanes at the same address (1 instruction, L1 broadcast — no
// shfl on the critical path).  Chebyshev recurrence fused into the epilogue.
__global__ void __launch_bounds__(256) k_spmm128(int in_off, int out_off,
                                                 int prev_off, int mode) {
    int warp = blockIdx.x * 8 + (threadIdx.x >> 5);
    int lane = threadIdx.x & 31;
    if (warp >= NNODES) return;
    int r = warp;
    int b = g_rowptr[r], e2 = g_rowptr[r + 1];
    int c = in_off + lane * 4;

    float4 acc0 = make_float4(0.f, 0.f, 0.f, 0.f);
    float4 acc1 = make_float4(0.f, 0.f, 0.f, 0.f);
    float4 acc2 = make_float4(0.f, 0.f, 0.f, 0.f);
    float4 acc3 = make_float4(0.f, 0.f, 0.f, 0.f);

    int e = b;
    for (; e + 4 <= e2; e += 4) {
        int2 h0 = g_edge[e];
        int2 h1 = g_edge[e + 1];
        int2 h2 = g_edge[e + 2];
        int2 h3 = g_edge[e + 3];
        float4 v0 = *(const float4*)&g_A[(size_t)h0.x * 512 + c];
        float4 v1 = *(const float4*)&g_A[(size_t)h1.x * 512 + c];
        float4 v2 = *(const float4*)&g_A[(size_t)h2.x * 512 + c];
        float4 v3 = *(const float4*)&g_A[(size_t)h3.x * 512 + c];
        float w0 = __int_as_float(h0.y), w1 = __int_as_float(h1.y);
        float w2 = __int_as_float(h2.y), w3 = __int_as_float(h3.y);
        acc0.x += w0 * v0.x; acc0.y += w0 * v0.y;
        acc0.z += w0 * v0.z; acc0.w += w0 * v0.w;
        acc1.x += w1 * v1.x; acc1.y += w1 * v1.y;
        acc1.z += w1 * v1.z; acc1.w += w1 * v1.w;
        acc2.x += w2 * v2.x; acc2.y += w2 * v2.y;
        acc2.z += w2 * v2.z; acc2.w += w2 * v2.w;
        acc3.x += w3 * v3.x; acc3.y += w3 * v3.y;
        acc3.z += w3 * v3.z; acc3.w += w3 * v3.w;
    }
    for (; e < e2; e++) {
        int2 h = g_edge[e];
        float w = __int_as_float(h.y);
        float4 v = *(const float4*)&g_A[(size_t)h.x * 512 + c];
        acc0.x += w * v.x; acc0.y += w * v.y;
        acc0.z += w * v.z; acc0.w += w * v.w;
    }
    float4 acc = make_float4((acc0.x + acc1.x) + (acc2.x + acc3.x),
                             (acc0.y + acc1.y) + (acc2.y + acc3.y),
                             (acc0.z + acc1.z) + (acc2.z + acc3.z),
                             (acc0.w + acc1.w) + (acc2.w + acc3.w));
    if (mode) {
        float4 pr = *(const float4*)&g_A[(size_t)r * 512 + prev_off + lane * 4];
        acc.x = 2.f * acc.x - pr.x;
        acc.y = 2.f * acc.y - pr.y;
        acc.z = 2.f * acc.z - pr.z;
        acc.w = 2.f * acc.w - pr.w;
    }
    *(float4*)&g_A[(size_t)r * 512 + out_off + lane * 4] = acc;
}

// ------------------------- K=512 fp32 GEMM (f32x2) -------------------------
// C[100000x128] = A[100000x512] * W[512x128] + bias, activation, and (when
// stats_layer >= 0) fused per-column BN-stat accumulation via smem reduction.
// BM=128, BN=128, BK=16, 256 threads, 8x8 micro-tile, packed FFMA2.
__global__ void __launch_bounds__(256, 2) k_gemm512(const float* __restrict__ W,
                                                    const float* __restrict__ bias,
                                                    int act, int stats_layer) {
    __shared__ __align__(16) float As[16][132];   // 2112 floats (reused for stats)
    __shared__ __align__(16) float Bs[16][128];   // 2048 floats (reused for stats)
    int tid = threadIdx.x;
    int row0 = blockIdx.x * 128;

    int a_m = tid >> 1;            // 0..127
    int a_k = (tid & 1) * 8;       // 0 or 8
    int b_k = tid >> 4;            // 0..15
    int b_n = (tid & 15) * 8;      // 0..120
    int tx = tid & 15, ty = tid >> 4;

    float2 acc[8][4];
#pragma unroll
    for (int i = 0; i < 8; i++)
#pragma unroll
        for (int j = 0; j < 4; j++) acc[i][j] = make_float2(0.f, 0.f);

    bool a_valid = (row0 + a_m) < NNODES;
    const float* Aptr = &g_A[(size_t)(a_valid ? (row0 + a_m) : 0) * 512 + a_k];
    const float* Wptr = W + b_k * 128 + b_n;

    for (int kt = 0; kt < 512; kt += 16) {
        float4 A0 = make_float4(0.f, 0.f, 0.f, 0.f), A1 = A0;
        if (a_valid) {
            A0 = *(const float4*)(Aptr + kt);
            A1 = *(const float4*)(Aptr + kt + 4);
        }
        float4 W0 = *(const float4*)(Wptr + (size_t)kt * 128);
        float4 W1 = *(const float4*)(Wptr + (size_t)kt * 128 + 4);

        As[a_k + 0][a_m] = A0.x; As[a_k + 1][a_m] = A0.y;
        As[a_k + 2][a_m] = A0.z; As[a_k + 3][a_m] = A0.w;
        As[a_k + 4][a_m] = A1.x; As[a_k + 5][a_m] = A1.y;
        As[a_k + 6][a_m] = A1.z; As[a_k + 7][a_m] = A1.w;
        *(float4*)&Bs[b_k][b_n] = W0;
        *(float4*)&Bs[b_k][b_n + 4] = W1;
        __syncthreads();

#pragma unroll
        for (int k = 0; k < 16; k++) {
            float4 af0 = *(const float4*)&As[k][ty * 8];
            float4 af1 = *(const float4*)&As[k][ty * 8 + 4];
            float2 bv0 = *(const float2*)&Bs[k][tx * 8];
            float2 bv1 = *(const float2*)&Bs[k][tx * 8 + 2];
            float2 bv2 = *(const float2*)&Bs[k][tx * 8 + 4];
            float2 bv3 = *(const float2*)&Bs[k][tx * 8 + 6];
            float av[8] = {af0.x, af0.y, af0.z, af0.w, af1.x, af1.y, af1.z, af1.w};
#pragma unroll
            for (int i = 0; i < 8; i++) {
                float2 ap = make_float2(av[i], av[i]);
                ffma2(acc[i][0], ap, bv0);
                ffma2(acc[i][1], ap, bv1);
                ffma2(acc[i][2], ap, bv2);
                ffma2(acc[i][3], ap, bv3);
            }
        }
        __syncthreads();
    }

    // epilogue: bias + activation + store; accumulate per-thread column stats
    float csum[8], csum2[8];
#pragma unroll
    for (int j = 0; j < 8; j++) { csum[j] = 0.f; csum2[j] = 0.f; }

#pragma unroll
    for (int i = 0; i < 8; i++) {
        int m = row0 + ty * 8 + i;
        if (m < NNODES) {
            float* yr = &g_Y[(size_t)m * 128 + tx * 8];
#pragma unroll
            for (int j = 0; j < 4; j++) {
                float2 v = acc[i][j];
                int n = tx * 8 + 2 * j;
                v.x += bias[n];
                v.y += bias[n + 1];
                if (act == 1) {
                    v.x = (v.x >= 0.f) ? v.x : NEG_SLOPE * v.x;
                    v.y = (v.y >= 0.f) ? v.y : NEG_SLOPE * v.y;
                } else if (act == 2) {
                    v.x = fmaxf(v.x, 0.f);
                    v.y = fmaxf(v.y, 0.f);
                }
                *(float2*)(yr + 2 * j) = v;
                csum[2 * j] += v.x;     csum[2 * j + 1] += v.y;
                csum2[2 * j] += v.x * v.x; csum2[2 * j + 1] += v.y * v.y;
            }
        }
    }

    if (stats_layer >= 0) {
        // block reduction over the 16 ty groups, via dead As/Bs smem
        float* ssum = &As[0][0];    // [16][128] flat (uses 2048 of 2112)
        float* ssum2 = &Bs[0][0];   // [16][128]
        __syncthreads();
#pragma unroll
        for (int j = 0; j < 8; j++) {
            ssum[ty * 128 + tx * 8 + j] = csum[j];
            ssum2[ty * 128 + tx * 8 + j] = csum2[j];
        }
        __syncthreads();
        if (tid < 128) {
            float s = 0.f, s2 = 0.f;
#pragma unroll
            for (int g = 0; g < 16; g++) {
                s += ssum[g * 128 + tid];
                s2 += ssum2[g * 128 + tid];
            }
            atomicAdd(&g_colsum[stats_layer][tid], s);
            atomicAdd(&g_colsumsq[stats_layer][tid], s2);
        }
    }
}

// -------------------- final: row L2 normalize + head -----------------------
__global__ void k_final(const float* __restrict__ Wrep,
                        const float* __restrict__ brep,
                        float* __restrict__ out) {
    int w = blockIdx.x * (blockDim.x >> 5) + (threadIdx.x >> 5);
    int lane = threadIdx.x & 31;
    if (w >= NNODES) return;
    const float* z = &g_Y[(size_t)w * 128];
    float v0 = z[lane], v1 = z[lane + 32], v2 = z[lane + 64], v3 = z[lane + 96];
    float ss = v0 * v0 + v1 * v1 + v2 * v2 + v3 * v3;
#pragma unroll
    for (int o = 16; o > 0; o >>= 1) ss += __shfl_xor_sync(0xffffffffu, ss, o);
    float invn = 1.0f / fmaxf(sqrtf(ss), 1e-12f);
    float d[3];
#pragma unroll
    for (int j = 0; j < 3; j++) {
        float t = v0 * Wrep[lane * 3 + j] + v1 * Wrep[(lane + 32) * 3 + j]
                + v2 * Wrep[(lane + 64) * 3 + j] + v3 * Wrep[(lane + 96) * 3 + j];
#pragma unroll
        for (int o = 16; o > 0; o >>= 1) t += __shfl_xor_sync(0xffffffffu, t, o);
        d[j] = t;
    }
    if (lane == 0) {
        out[(size_t)w * 3 + 0] = d[0] * invn + brep[0];
        out[(size_t)w * 3 + 1] = d[1] * invn + brep[1];
        out[(size_t)w * 3 + 2] = d[2] * invn + brep[2];
    }
}

// ------------------------------- launch ------------------------------------
extern "C" void kernel_launch(void* const* d_in, const int* in_sizes, int n_in,
                              void* d_out, int out_size) {
    const float* x    = (const float*)d_in[0];
    const int*   ed   = (const int*)d_in[1];
    const float* W1   = (const float*)d_in[2];
    const float* b1   = (const float*)d_in[3];
    const float* W2   = (const float*)d_in[4];
    const float* b2   = (const float*)d_in[5];
    const float* W3   = (const float*)d_in[6];
    const float* b3   = (const float*)d_in[7];
    const float* W4   = (const float*)d_in[8];
    const float* b4   = (const float*)d_in[9];
    const float* g1   = (const float*)d_in[10];
    const float* be1  = (const float*)d_in[11];
    const float* g2   = (const float*)d_in[12];
    const float* be2  = (const float*)d_in[13];
    const float* g3   = (const float*)d_in[14];
    const float* be3  = (const float*)d_in[15];
    const float* Wrep = (const float*)d_in[16];
    const float* brep = (const float*)d_in[17];
    float* out = (float*)d_out;

    const int GEMM_GRID = (NNODES + 127) / 128;   // 782
    const int SPMM_GRID = (NNODES + 7) / 8;       // 12500

    // CSR build (+ staging x into layer-1 block)
    k_init<<<392, 256>>>(x);
    k_detect<<<1, 32>>>(ed, in_sizes[1]);
    k_count<<<512, 256>>>(ed);
    k_scan<<<1, 1024>>>();
    k_fill<<<512, 256>>>(ed);

    // ---- layer 1 (3 -> 128, leaky + BN1) ----
    k_spmm3<<<392, 256>>>(0, 3, 0, 0);
    k_spmm3<<<392, 256>>>(3, 6, 0, 1);
    k_spmm3<<<392, 256>>>(6, 9, 3, 1);
    k_gemm12<<<1024, 128>>>(W1, b1);
    k_apply<<<1024, 256>>>(g1, be1, 0);

    // ---- layer 2 (leaky + BN2) ----
    k_spmm128<<<SPMM_GRID, 256>>>(0, 128, 0, 0);
    k_spmm128<<<SPMM_GRID, 256>>>(128, 256, 0, 1);
    k_spmm128<<<SPMM_GRID, 256>>>(256, 384, 128, 1);
    k_gemm512<<<GEMM_GRID, 256>>>(W2, b2, 1, 1);
    k_apply<<<1024, 256>>>(g2, be2, 1);

    // ---- layer 3 (relu + BN3) ----
    k_spmm128<<<SPMM_GRID, 256>>>(0, 128, 0, 0);
    k_spmm128<<<SPMM_GRID, 256>>>(128, 256, 0, 1);
    k_spmm128<<<SPMM_GRID, 256>>>(256, 384, 128, 1);
    k_gemm512<<<GEMM_GRID, 256>>>(W3, b3, 2, 2);
    k_apply<<<1024, 256>>>(g3, be3, 2);

    // ---- layer 4 (no act) + L2-normalize + head ----
    k_spmm128<<<SPMM_GRID, 256>>>(0, 128, 0, 0);
    k_spmm128<<<SPMM_GRID, 256>>>(128, 256, 0, 1);
    k_spmm128<<<SPMM_GRID, 256>>>(256, 384, 128, 1);
    k_gemm512<<<GEMM_GRID, 256>>>(W4, b4, 0, -1);
    k_final<<<(NNODES + 7) / 8, 256>>>(Wrep, brep, out);
}

// round 10
// speedup vs baseline: 1.0516x; 1.0516x over previous
#include <cuda_runtime.h>

// ---------------------------------------------------------------------------
// ChebConv x4 GNN on GB300.  N=100000 nodes, E=1600000 directed edges
// (symmetrized), HID=128, K=4 Chebyshev order.
//
// R8:  serial scan -> warp-aggregated atomic slice allocation (~8us).
// R9:  2-stage double-buffered GEMM mainloop (1 barrier/tile).
// R10: edge-stride detection folded into k_init (one fewer launch).
// ---------------------------------------------------------------------------

#define NNODES 100000
#define NEDGES 1600000
#define HIDDEN 128
#define NEG_SLOPE 0.01f

// ------------------------------- scratch -----------------------------------
__device__ float g_A[(size_t)NNODES * 512];   // [T0|T1|T2|T3] per row, 512 f32
__device__ float g_Y[(size_t)NNODES * HIDDEN];
__device__ float g_A1[(size_t)NNODES * 12];   // layer-1 [T0|T1|T2|T3] x 3
__device__ int   g_deg[NNODES];
__device__ int   g_cur[NNODES];
__device__ int   g_rowstart[NNODES];
__device__ int2  g_edge[NEDGES];              // (col, enorm-bits) interleaved
__device__ float g_dinv[NNODES];
__device__ float g_colsum[3][HIDDEN];         // per-BN-layer stats
__device__ float g_colsumsq[3][HIDDEN];
__device__ int   g_estride;                   // 1 = int32 edges, 2 = int64
__device__ int   g_total;                     // edge-slice allocation counter

// ------------------------------ helpers ------------------------------------
__device__ __forceinline__ void ffma2(float2& d, const float2 a, const float2 b) {
    asm volatile("fma.rn.f32x2 %0, %1, %2, %0;"
                 : "+l"(reinterpret_cast<unsigned long long&>(d))
                 : "l"(reinterpret_cast<const unsigned long long&>(a)),
                   "l"(reinterpret_cast<const unsigned long long&>(b)));
}

// ------------------------------ CSR build ----------------------------------
// init counters + stage x into the layer-1 feature block + edge-stride detect
// (int64 little-endian: every odd 32-bit word is a zero high-word since all
// indices < 100000; random int32 edge values make the test robust).
__global__ void k_init(const float* __restrict__ x, const int* __restrict__ ed) {
    int i = blockIdx.x * blockDim.x + threadIdx.x;
    int gs = gridDim.x * blockDim.x;
    for (int j = i; j < NNODES; j += gs) {
        g_deg[j] = 0;
        g_cur[j] = 0;
        g_A1[j * 12 + 0] = x[j * 3 + 0];
        g_A1[j * 12 + 1] = x[j * 3 + 1];
        g_A1[j * 12 + 2] = x[j * 3 + 2];
    }
    if (blockIdx.x == 0) {
        if (threadIdx.x == 0) g_total = 0;
        if (threadIdx.x < HIDDEN) {
            for (int l = 0; l < 3; l++) {
                g_colsum[l][threadIdx.x] = 0.f;
                g_colsumsq[l][threadIdx.x] = 0.f;
            }
        }
        if (threadIdx.x < 32) {
            int lane = threadIdx.x;
            bool any = false;
            for (int k2 = 1 + 2 * lane; k2 < 4096; k2 += 64) any |= (ed[k2] != 0);
            any = __any_sync(0xffffffffu, any);
            if (lane == 0) g_estride = any ? 1 : 2;
        }
    }
}

// dst = second row of edge_index; coalesced 64-bit reads in the int64 case.
__global__ void k_count(const int* __restrict__ ed) {
    int st = g_estride;
    int i = blockIdx.x * blockDim.x + threadIdx.x;
    int gs = gridDim.x * blockDim.x;
    if (st == 1) {
        const int* dstp = ed + NEDGES;
        for (int e = i; e < NEDGES; e += gs)
            atomicAdd(&g_deg[dstp[e]], 1);
    } else {
        const long long* dstp = (const long long*)ed + NEDGES;
        for (int e = i; e < NEDGES; e += gs)
            atomicAdd(&g_deg[(int)dstp[e]], 1);
    }
}

// Allocate each row a contiguous slice of g_edge via warp-aggregated atomics
// (replaces the serial single-block scan).  Also computes dinv = rsqrt(deg).
__global__ void k_alloc() {
    const int NPAD = (NNODES + 31) & ~31;     // keep full warps active
    int i = blockIdx.x * blockDim.x + threadIdx.x;
    int gs = gridDim.x * blockDim.x;
    int lane = threadIdx.x & 31;
    for (int j = i; j < NPAD; j += gs) {
        int d = (j < NNODES) ? g_deg[j] : 0;
        int pre = d;
#pragma unroll
        for (int o = 1; o < 32; o <<= 1) {
            int v = __shfl_up_sync(0xffffffffu, pre, o);
            if (lane >= o) pre += v;
        }
        int wtot = __shfl_sync(0xffffffffu, pre, 31);
        int base = 0;
        if (lane == 31) base = atomicAdd(&g_total, wtot);
        base = __shfl_sync(0xffffffffu, base, 31);
        if (j < NNODES) {
            g_rowstart[j] = base + pre - d;
            g_dinv[j] = (d > 0) ? rsqrtf((float)d) : 0.f;
        }
    }
}

__global__ void k_fill(const int* __restrict__ ed) {
    int st = g_estride;
    int i = blockIdx.x * blockDim.x + threadIdx.x;
    int gs = gridDim.x * blockDim.x;
    if (st == 1) {
        const int* srcp = ed;
        const int* dstp = ed + NEDGES;
        for (int e = i; e < NEDGES; e += gs) {
            int s = srcp[e], d = dstp[e];
            int pos = g_rowstart[d] + atomicAdd(&g_cur[d], 1);
            float w = -g_dinv[s] * g_dinv[d];
            g_edge[pos] = make_int2(s, __float_as_int(w));
        }
    } else {
        const long long* srcp = (const long long*)ed;
        const long long* dstp = (const long long*)ed + NEDGES;
        for (int e = i; e < NEDGES; e += gs) {
            int s = (int)srcp[e], d = (int)dstp[e];
            int pos = g_rowstart[d] + atomicAdd(&g_cur[d], 1);
            float w = -g_dinv[s] * g_dinv[d];
            g_edge[pos] = make_int2(s, __float_as_int(w));
        }
    }
}

// --------------------------- layer 1 (3-wide) ------------------------------
__global__ void k_spmm3(int in_off, int out_off, int prev_off, int mode) {
    int i = blockIdx.x * blockDim.x + threadIdx.x;
    int gs = gridDim.x * blockDim.x;
    for (int r = i; r < NNODES; r += gs) {
        int b = g_rowstart[r], e2 = b + g_deg[r];
        float a0 = 0.f, a1 = 0.f, a2 = 0.f;
        for (int e = b; e < e2; e++) {
            int2 ew = g_edge[e];
            float w = __int_as_float(ew.y);
            const float* p = &g_A1[(size_t)ew.x * 12 + in_off];
            a0 += w * p[0]; a1 += w * p[1]; a2 += w * p[2];
        }
        if (mode) {
            const float* pr = &g_A1[(size_t)r * 12 + prev_off];
            a0 = 2.f * a0 - pr[0]; a1 = 2.f * a1 - pr[1]; a2 = 2.f * a2 - pr[2];
        }
        float* q = &g_A1[(size_t)r * 12 + out_off];
        q[0] = a0; q[1] = a1; q[2] = a2;
    }
}

// K=12 GEMM + leaky + fused BN-stats accumulation (layer-0 stats).
__global__ void k_gemm12(const float* __restrict__ W, const float* __restrict__ bias) {
    __shared__ float Ws[12 * 128];
    int c = threadIdx.x;
    for (int j = 0; j < 12; j++) Ws[j * 128 + c] = W[j * 128 + c];
    __syncthreads();
    float b = bias[c];
    float s = 0.f, s2 = 0.f;
    for (int i = blockIdx.x; i < NNODES; i += gridDim.x) {
        const float* ar = &g_A1[(size_t)i * 12];
        float acc = b;
#pragma unroll
        for (int j = 0; j < 12; j++) acc += ar[j] * Ws[j * 128 + c];
        acc = (acc >= 0.f) ? acc : NEG_SLOPE * acc;   // leaky
        g_Y[(size_t)i * 128 + c] = acc;
        s += acc; s2 += acc * acc;
    }
    atomicAdd(&g_colsum[0][c], s);
    atomicAdd(&g_colsumsq[0][c], s2);
}

// ------------------------------ BN apply ------------------------------------
__global__ void __launch_bounds__(256) k_apply(const float* __restrict__ gamma,
                                               const float* __restrict__ beta,
                                               int layer) {
    __shared__ float s_scale[HIDDEN];
    __shared__ float s_shift[HIDDEN];
    int t = threadIdx.x;
    if (t < HIDDEN) {
        const float inv_n = 1.0f / (float)NNODES;
        float mu = g_colsum[layer][t] * inv_n;
        float var = fmaxf(g_colsumsq[layer][t] * inv_n - mu * mu, 0.f);
        float sc = gamma[t] * rsqrtf(var + 1e-5f);
        s_scale[t] = sc;
        s_shift[t] = beta[t] - mu * sc;
    }
    __syncthreads();

    int i = blockIdx.x * blockDim.x + t;
    int gs = gridDim.x * blockDim.x;
    const int tot = NNODES * 32;   // float4 groups
    for (int idx = i; idx < tot; idx += gs) {
        int row = idx >> 5;
        int c4 = idx & 31;
        float4 y = *(const float4*)&g_Y[(size_t)row * 128 + c4 * 4];
        float4 sc = *(const float4*)&s_scale[c4 * 4];
        float4 sh = *(const float4*)&s_shift[c4 * 4];
        float4 r;
        r.x = y.x * sc.x + sh.x;
        r.y = y.y * sc.y + sh.y;
        r.z = y.z * sc.z + sh.z;
        r.w = y.w * sc.w + sh.w;
        *(float4*)&g_A[(size_t)row * 512 + c4 * 4] = r;
    }
}

// --------------------------- 128-wide SpMM ---------------------------------
// Warp per row; each lane owns 4 consecutive columns (float4).  Edge headers
// loaded by ALL lanes at the same address (1 instruction, L1 broadcast).
// Chebyshev recurrence fused into the epilogue.
__global__ void __launch_bounds__(256) k_spmm128(int in_off, int out_off,
                                                 int prev_off, int mode) {
    int warp = blockIdx.x * 8 + (threadIdx.x >> 5);
    int lane = threadIdx.x & 31;
    if (warp >= NNODES) return;
    int r = warp;
    int b = g_rowstart[r], e2 = b + g_deg[r];
    int c = in_off + lane * 4;

    float4 acc0 = make_float4(0.f, 0.f, 0.f, 0.f);
    float4 acc1 = make_float4(0.f, 0.f, 0.f, 0.f);
    float4 acc2 = make_float4(0.f, 0.f, 0.f, 0.f);
    float4 acc3 = make_float4(0.f, 0.f, 0.f, 0.f);

    int e = b;
    for (; e + 4 <= e2; e += 4) {
        int2 h0 = g_edge[e];
        int2 h1 = g_edge[e + 1];
        int2 h2 = g_edge[e + 2];
        int2 h3 = g_edge[e + 3];
        float4 v0 = *(const float4*)&g_A[(size_t)h0.x * 512 + c];
        float4 v1 = *(const float4*)&g_A[(size_t)h1.x * 512 + c];
        float4 v2 = *(const float4*)&g_A[(size_t)h2.x * 512 + c];
        float4 v3 = *(const float4*)&g_A[(size_t)h3.x * 512 + c];
        float w0 = __int_as_float(h0.y), w1 = __int_as_float(h1.y);
        float w2 = __int_as_float(h2.y), w3 = __int_as_float(h3.y);
        acc0.x += w0 * v0.x; acc0.y += w0 * v0.y;
        acc0.z += w0 * v0.z; acc0.w += w0 * v0.w;
        acc1.x += w1 * v1.x; acc1.y += w1 * v1.y;
        acc1.z += w1 * v1.z; acc1.w += w1 * v1.w;
        acc2.x += w2 * v2.x; acc2.y += w2 * v2.y;
        acc2.z += w2 * v2.z; acc2.w += w2 * v2.w;
        acc3.x += w3 * v3.x; acc3.y += w3 * v3.y;
        acc3.z += w3 * v3.z; acc3.w += w3 * v3.w;
    }
    for (; e < e2; e++) {
        int2 h = g_edge[e];
        float w = __int_as_float(h.y);
        float4 v = *(const float4*)&g_A[(size_t)h.x * 512 + c];
        acc0.x += w * v.x; acc0.y += w * v.y;
        acc0.z += w * v.z; acc0.w += w * v.w;
    }
    float4 acc = make_float4((acc0.x + acc1.x) + (acc2.x + acc3.x),
                             (acc0.y + acc1.y) + (acc2.y + acc3.y),
                             (acc0.z + acc1.z) + (acc2.z + acc3.z),
                             (acc0.w + acc1.w) + (acc2.w + acc3.w));
    if (mode) {
        float4 pr = *(const float4*)&g_A[(size_t)r * 512 + prev_off + lane * 4];
        acc.x = 2.f * acc.x - pr.x;
        acc.y = 2.f * acc.y - pr.y;
        acc.z = 2.f * acc.z - pr.z;
        acc.w = 2.f * acc.w - pr.w;
    }
    *(float4*)&g_A[(size_t)r * 512 + out_off + lane * 4] = acc;
}

// ------------------------- K=512 fp32 GEMM (f32x2) -------------------------
// C[100000x128] = A[100000x512] * W[512x128] + bias, activation, and (when
// stats_layer >= 0) fused per-column BN-stat accumulation via smem reduction.
// BM=128, BN=128, BK=16, 256 threads, 8x8 micro-tile, packed FFMA2.
// 2-stage double-buffered smem pipeline: one barrier per K-tile; next tile's
// global loads issued before compute of the current tile.
__global__ void __launch_bounds__(256, 2) k_gemm512(const float* __restrict__ W,
                                                    const float* __restrict__ bias,
                                                    int act, int stats_layer) {
    __shared__ __align__(16) float As[2][16][132];
    __shared__ __align__(16) float Bs[2][16][128];
    int tid = threadIdx.x;
    int row0 = blockIdx.x * 128;

    int a_m = tid >> 1;            // 0..127
    int a_k = (tid & 1) * 8;       // 0 or 8
    int b_k = tid >> 4;            // 0..15
    int b_n = (tid & 15) * 8;      // 0..120
    int tx = tid & 15, ty = tid >> 4;

    float2 acc[8][4];
#pragma unroll
    for (int i = 0; i < 8; i++)
#pragma unroll
        for (int j = 0; j < 4; j++) acc[i][j] = make_float2(0.f, 0.f);

    bool a_valid = (row0 + a_m) < NNODES;
    const float* Aptr = &g_A[(size_t)(a_valid ? (row0 + a_m) : 0) * 512 + a_k];
    const float* Wptr = W + b_k * 128 + b_n;

    const int NT = 32;   // 512 / 16 K-tiles
    float4 A0 = make_float4(0.f, 0.f, 0.f, 0.f), A1 = A0, W0, W1;

    // prologue: load tile 0 and stage it
    if (a_valid) {
        A0 = *(const float4*)(Aptr + 0);
        A1 = *(const float4*)(Aptr + 4);
    }
    W0 = *(const float4*)(Wptr);
    W1 = *(const float4*)(Wptr + 4);
    As[0][a_k + 0][a_m] = A0.x; As[0][a_k + 1][a_m] = A0.y;
    As[0][a_k + 2][a_m] = A0.z; As[0][a_k + 3][a_m] = A0.w;
    As[0][a_k + 4][a_m] = A1.x; As[0][a_k + 5][a_m] = A1.y;
    As[0][a_k + 6][a_m] = A1.z; As[0][a_k + 7][a_m] = A1.w;
    *(float4*)&Bs[0][b_k][b_n] = W0;
    *(float4*)&Bs[0][b_k][b_n + 4] = W1;

    for (int t = 0; t < NT; t++) {
        int cur = t & 1;
        // issue next tile's global loads (latency hidden under compute)
        if (t + 1 < NT) {
            int kt = (t + 1) * 16;
            A0 = make_float4(0.f, 0.f, 0.f, 0.f); A1 = A0;
            if (a_valid) {
                A0 = *(const float4*)(Aptr + kt);
                A1 = *(const float4*)(Aptr + kt + 4);
            }
            W0 = *(const float4*)(Wptr + (size_t)kt * 128);
            W1 = *(const float4*)(Wptr + (size_t)kt * 128 + 4);
        }
        __syncthreads();   // stage `cur` fully written (stores from iter t-1)

#pragma unroll
        for (int k = 0; k < 16; k++) {
            float4 af0 = *(const float4*)&As[cur][k][ty * 8];
            float4 af1 = *(const float4*)&As[cur][k][ty * 8 + 4];
            float2 bv0 = *(const float2*)&Bs[cur][k][tx * 8];
            float2 bv1 = *(const float2*)&Bs[cur][k][tx * 8 + 2];
            float2 bv2 = *(const float2*)&Bs[cur][k][tx * 8 + 4];
            float2 bv3 = *(const float2*)&Bs[cur][k][tx * 8 + 6];
            float av[8] = {af0.x, af0.y, af0.z, af0.w, af1.x, af1.y, af1.z, af1.w};
#pragma unroll
            for (int i = 0; i < 8; i++) {
                float2 ap = make_float2(av[i], av[i]);
                ffma2(acc[i][0], ap, bv0);
                ffma2(acc[i][1], ap, bv1);
                ffma2(acc[i][2], ap, bv2);
                ffma2(acc[i][3], ap, bv3);
            }
        }

        // stage next tile into the other buffer (safe: everyone finished
        // reading it at the barrier above)
        if (t + 1 < NT) {
            int nxt = (t + 1) & 1;
            As[nxt][a_k + 0][a_m] = A0.x; As[nxt][a_k + 1][a_m] = A0.y;
            As[nxt][a_k + 2][a_m] = A0.z; As[nxt][a_k + 3][a_m] = A0.w;
            As[nxt][a_k + 4][a_m] = A1.x; As[nxt][a_k + 5][a_m] = A1.y;
            As[nxt][a_k + 6][a_m] = A1.z; As[nxt][a_k + 7][a_m] = A1.w;
            *(float4*)&Bs[nxt][b_k][b_n] = W0;
            *(float4*)&Bs[nxt][b_k][b_n + 4] = W1;
        }
    }

    // epilogue: bias + activation + store; accumulate per-thread column stats
    float csum[8], csum2[8];
#pragma unroll
    for (int j = 0; j < 8; j++) { csum[j] = 0.f; csum2[j] = 0.f; }

#pragma unroll
    for (int i = 0; i < 8; i++) {
        int m = row0 + ty * 8 + i;
        if (m < NNODES) {
            float* yr = &g_Y[(size_t)m * 128 + tx * 8];
#pragma unroll
            for (int j = 0; j < 4; j++) {
                float2 v = acc[i][j];
                int n = tx * 8 + 2 * j;
                v.x += bias[n];
                v.y += bias[n + 1];
                if (act == 1) {
                    v.x = (v.x >= 0.f) ? v.x : NEG_SLOPE * v.x;
                    v.y = (v.y >= 0.f) ? v.y : NEG_SLOPE * v.y;
                } else if (act == 2) {
                    v.x = fmaxf(v.x, 0.f);
                    v.y = fmaxf(v.y, 0.f);
                }
                *(float2*)(yr + 2 * j) = v;
                csum[2 * j] += v.x;     csum[2 * j + 1] += v.y;
                csum2[2 * j] += v.x * v.x; csum2[2 * j + 1] += v.y * v.y;
            }
        }
    }

    if (stats_layer >= 0) {
        // block reduction over the 16 ty groups, via dead smem
        float* ssum = &As[0][0][0];    // needs 2048 floats
        float* ssum2 = &Bs[0][0][0];   // needs 2048 floats
        __syncthreads();
#pragma unroll
        for (int j = 0; j < 8; j++) {
            ssum[ty * 128 + tx * 8 + j] = csum[j];
            ssum2[ty * 128 + tx * 8 + j] = csum2[j];
        }
        __syncthreads();
        if (tid < 128) {
            float s = 0.f, s2 = 0.f;
#pragma unroll
            for (int g = 0; g < 16; g++) {
                s += ssum[g * 128 + tid];
                s2 += ssum2[g * 128 + tid];
            }
            atomicAdd(&g_colsum[stats_layer][tid], s);
            atomicAdd(&g_colsumsq[stats_layer][tid], s2);
        }
    }
}

// -------------------- final: row L2 normalize + head -----------------------
__global__ void k_final(const float* __restrict__ Wrep,
                        const float* __restrict__ brep,
                        float* __restrict__ out) {
    int w = blockIdx.x * (blockDim.x >> 5) + (threadIdx.x >> 5);
    int lane = threadIdx.x & 31;
    if (w >= NNODES) return;
    const float* z = &g_Y[(size_t)w * 128];
    float v0 = z[lane], v1 = z[lane + 32], v2 = z[lane + 64], v3 = z[lane + 96];
    float ss = v0 * v0 + v1 * v1 + v2 * v2 + v3 * v3;
#pragma unroll
    for (int o = 16; o > 0; o >>= 1) ss += __shfl_xor_sync(0xffffffffu, ss, o);
    float invn = 1.0f / fmaxf(sqrtf(ss), 1e-12f);
    float d[3];
#pragma unroll
    for (int j = 0; j < 3; j++) {
        float t = v0 * Wrep[lane * 3 + j] + v1 * Wrep[(lane + 32) * 3 + j]
                + v2 * Wrep[(lane + 64) * 3 + j] + v3 * Wrep[(lane + 96) * 3 + j];
#pragma unroll
        for (int o = 16; o > 0; o >>= 1) t += __shfl_xor_sync(0xffffffffu, t, o);
        d[j] = t;
    }
    if (lane == 0) {
        out[(size_t)w * 3 + 0] = d[0] * invn + brep[0];
        out[(size_t)w * 3 + 1] = d[1] * invn + brep[1];
        out[(size_t)w * 3 + 2] = d[2] * invn + brep[2];
    }
}

// ------------------------------- launch ------------------------------------
extern "C" void kernel_launch(void* const* d_in, const int* in_sizes, int n_in,
                              void* d_out, int out_size) {
    const float* x    = (const float*)d_in[0];
    const int*   ed   = (const int*)d_in[1];
    const float* W1   = (const float*)d_in[2];
    const float* b1   = (const float*)d_in[3];
    const float* W2   = (const float*)d_in[4];
    const float* b2   = (const float*)d_in[5];
    const float* W3   = (const float*)d_in[6];
    const float* b3   = (const float*)d_in[7];
    const float* W4   = (const float*)d_in[8];
    const float* b4   = (const float*)d_in[9];
    const float* g1   = (const float*)d_in[10];
    const float* be1  = (const float*)d_in[11];
    const float* g2   = (const float*)d_in[12];
    const float* be2  = (const float*)d_in[13];
    const float* g3   = (const float*)d_in[14];
    const float* be3  = (const float*)d_in[15];
    const float* Wrep = (const float*)d_in[16];
    const float* brep = (const float*)d_in[17];
    float* out = (float*)d_out;

    const int GEMM_GRID = (NNODES + 127) / 128;   // 782
    const int SPMM_GRID = (NNODES + 7) / 8;       // 12500

    // CSR build (+ staging x, stride detect)
    k_init<<<392, 256>>>(x, ed);
    k_count<<<512, 256>>>(ed);
    k_alloc<<<392, 256>>>();
    k_fill<<<512, 256>>>(ed);

    // ---- layer 1 (3 -> 128, leaky + BN1) ----
    k_spmm3<<<392, 256>>>(0, 3, 0, 0);
    k_spmm3<<<392, 256>>>(3, 6, 0, 1);
    k_spmm3<<<392, 256>>>(6, 9, 3, 1);
    k_gemm12<<<1024, 128>>>(W1, b1);
    k_apply<<<1024, 256>>>(g1, be1, 0);

    // ---- layer 2 (leaky + BN2) ----
    k_spmm128<<<SPMM_GRID, 256>>>(0, 128, 0, 0);
    k_spmm128<<<SPMM_GRID, 256>>>(128, 256, 0, 1);
    k_spmm128<<<SPMM_GRID, 256>>>(256, 384, 128, 1);
    k_gemm512<<<GEMM_GRID, 256>>>(W2, b2, 1, 1);
    k_apply<<<1024, 256>>>(g2, be2, 1);

    // ---- layer 3 (relu + BN3) ----
    k_spmm128<<<SPMM_GRID, 256>>>(0, 128, 0, 0);
    k_spmm128<<<SPMM_GRID, 256>>>(128, 256, 0, 1);
    k_spmm128<<<SPMM_GRID, 256>>>(256, 384, 128, 1);
    k_gemm512<<<GEMM_GRID, 256>>>(W3, b3, 2, 2);
    k_apply<<<1024, 256>>>(g3, be3, 2);

    // ---- layer 4 (no act) + L2-normalize + head ----
    k_spmm128<<<SPMM_GRID, 256>>>(0, 128, 0, 0);
    k_spmm128<<<SPMM_GRID, 256>>>(128, 256, 0, 1);
    k_spmm128<<<SPMM_GRID, 256>>>(256, 384, 128, 1);
    k_gemm512<<<GEMM_GRID, 256>>>(W4, b4, 0, -1);
    k_final<<<(NNODES + 7) / 8, 256>>>(Wrep, brep, out);
}